// round 11
// baseline (speedup 1.0000x reference)
#include <cuda_runtime.h>
#include <math_constants.h>

// Chamfer distance, B=16 events, P=Q=4096, 3D — R11: exact NN via x-sorted
// windows. Counting-sort each (set,event) by x; per query, probe 16
// candidates near its x-rank for an upper bound UB, scan only candidates
// with |dx| <= sqrt(UB) (bin-granular window). Warp = 32 sorted queries,
// coalesced candidate loads, smem query broadcast, register min matrix,
// transposed warp reduction. Exact min => deterministic despite atomic sort.

#define NB 16
#define NP 4096
#define NPTS (NB * NP)          // 65536 per set
#define NQ_TOTAL (2 * NPTS)     // 131072
#define NBINS 256

#define SORT_THREADS 256
#define NN_THREADS 256
#define SUM_THREADS 256
#define SUM_BLOCKS 128
#define PER_BLOCK (NQ_TOTAL / SUM_BLOCKS)       // 1024
#define PER_THREAD (PER_BLOCK / SUM_THREADS)    // 4

// set 0 = gen (normal, x-range ~±3.3), set 1 = gt (normalized to [-1,1))
__device__ float4 g_sorted[2][NPTS];
__device__ int    g_sortidx[2][NPTS];
__device__ int    g_binstart[2][NB][NBINS + 1];
__device__ float  g_best[NQ_TOTAL];
__device__ float  g_part[SUM_BLOCKS];
__device__ unsigned int g_sync;   // zero-init; reset by sum kernel

__device__ __forceinline__ int bin_of(float x, float invs) {
    int k = (int)((x * invs + 1.0f) * (NBINS / 2));
    return min(max(k, 0), NBINS - 1);
}

__global__ __launch_bounds__(SORT_THREADS)
void sort_kernel(const float* __restrict__ gen,
                 const float* __restrict__ label) {
    __shared__ int cnt[NBINS];
    __shared__ int offs[NBINS];
    const int s = blockIdx.x >> 4;      // set
    const int b = blockIdx.x & 15;      // event
    const int t = threadIdx.x;
    const float invs = (s == 0) ? (1.0f / 3.3f) : 1.0f;

    for (int k = t; k < NBINS; k += SORT_THREADS) cnt[k] = 0;
    __syncthreads();

    for (int i = t; i < NP; i += SORT_THREADS) {
        float x;
        if (s == 0) x = gen[(size_t)(b * NP + i) * 3];
        else        x = (label[(size_t)(b * NP + i) * 5 + 1] - 128.0f) * (1.0f / 128.0f);
        atomicAdd(&cnt[bin_of(x, invs)], 1);
    }
    __syncthreads();

    if (t == 0) {
        int acc = 0;
        for (int k = 0; k < NBINS; k++) {
            offs[k] = acc;
            g_binstart[s][b][k] = acc;
            acc += cnt[k];
        }
        g_binstart[s][b][NBINS] = acc;   // == NP
    }
    __syncthreads();

    for (int i = t; i < NP; i += SORT_THREADS) {
        float x, y, z;
        if (s == 0) {
            const float* p = gen + (size_t)(b * NP + i) * 3;
            x = p[0]; y = p[1]; z = p[2];
        } else {
            const float* p = label + (size_t)(b * NP + i) * 5 + 1;
            x = (p[0] - 128.0f) * (1.0f / 128.0f);
            y = (p[1] - 128.0f) * (1.0f / 128.0f);
            z = (p[2] - 128.0f) * (1.0f / 128.0f);
        }
        int pos = atomicAdd(&offs[bin_of(x, invs)], 1);
        g_sorted[s][b * NP + pos] = make_float4(x, y, z, x * x + y * y + z * z);
        g_sortidx[s][b * NP + pos] = s * NPTS + b * NP + i;
    }
}

__global__ __launch_bounds__(NN_THREADS)
void nn_kernel() {
    __shared__ float4 qsc[NN_THREADS];          // pre-scaled (-2x,-2y,-2z, |q|^2)
    __shared__ float  tw[NN_THREADS / 32][32 * 33];
    __shared__ int    sb[NBINS + 1];

    const int t = threadIdx.x;
    const int wid = t >> 5, lane = t & 31;
    const int gq = blockIdx.x * NN_THREADS;     // global query base (sorted order)
    const int qs = gq / NPTS;                   // query set == direction
    const int cs = 1 - qs;                      // candidate set
    const int within = gq % NPTS;
    const int e = within / NP;
    const int qoff = within % NP;
    const float invs_c = (cs == 0) ? (1.0f / 3.3f) : 1.0f;

    for (int k = t; k < NBINS + 1; k += NN_THREADS)
        sb[k] = g_binstart[cs][e][k];
    {
        float4 v = g_sorted[qs][e * NP + qoff + t];
        qsc[t] = make_float4(-2.0f * v.x, -2.0f * v.y, -2.0f * v.z, v.w);
    }
    __syncthreads();

    const float4* __restrict__ cand = &g_sorted[cs][e * NP];

    // ---- per-lane upper bound: probe 16 candidates near query's x-rank ----
    float4 mq = qsc[wid * 32 + lane];
    float qx = -0.5f * mq.x;
    int p0 = sb[bin_of(qx, invs_c)];
    int phi = min(p0 + 8, NP);
    int plo = max(phi - 16, 0);
    float ub = CUDART_INF_F;
#pragma unroll 4
    for (int i = plo; i < plo + 16; i++) {
        float4 c = cand[i];
        float d = fmaf(c.x, mq.x, fmaf(c.y, mq.y, fmaf(c.z, mq.z, mq.w))) + c.w;
        ub = fminf(ub, d);
    }
    float rw = sqrtf(ub);
    float xl = qx - rw, xh = qx + rw;
    // warp union window (all 32 queries share one scan range)
#pragma unroll
    for (int o = 16; o > 0; o >>= 1) {
        xl = fminf(xl, __shfl_xor_sync(0xffffffffu, xl, o));
        xh = fmaxf(xh, __shfl_xor_sync(0xffffffffu, xh, o));
    }
    const int ilo = sb[bin_of(xl, invs_c)];
    const int ihi = sb[bin_of(xh, invs_c) + 1];

    // ---- scan: lane = candidate (coalesced), loop 32 queries (broadcast) ----
    float mymin[32];
#pragma unroll
    for (int q = 0; q < 32; q++) mymin[q] = CUDART_INF_F;

    const float4* qw = &qsc[wid * 32];
    for (int base = ilo; base < ihi; base += 32) {
        int i = base + lane;
        if (i >= ihi) i = ihi - 1;        // duplicate tail: harmless for min
        float4 c = cand[i];
#pragma unroll
        for (int q = 0; q < 32; q++) {
            float4 qv = qw[q];
            float d = fmaf(c.x, qv.x, fmaf(c.y, qv.y, fmaf(c.z, qv.z, qv.w))) + c.w;
            mymin[q] = fminf(mymin[q], d);
        }
    }

    // ---- transpose + per-query reduction across lanes ----
    float* w = tw[wid];
#pragma unroll
    for (int q = 0; q < 32; q++) w[lane * 33 + q] = mymin[q];
    __syncwarp();
    float bestq = CUDART_INF_F;
#pragma unroll
    for (int l = 0; l < 32; l++) bestq = fminf(bestq, w[l * 33 + lane]);

    int oidx = g_sortidx[qs][e * NP + qoff + wid * 32 + lane];
    g_best[oidx] = bestq;   // lane reduces query 'lane' of this warp
}

__global__ __launch_bounds__(SUM_THREADS)
void sum_kernel(float* __restrict__ out) {
    __shared__ float red[SUM_THREADS / 32];
    __shared__ unsigned int is_last;
    const int t = threadIdx.x;
    const int blk = blockIdx.x;

    float s = 0.0f;
#pragma unroll
    for (int i = 0; i < PER_THREAD; i++)
        s += __ldcg(&g_best[blk * PER_BLOCK + i * SUM_THREADS + t]);

#pragma unroll
    for (int o = 16; o > 0; o >>= 1)
        s += __shfl_down_sync(0xffffffffu, s, o);
    if ((t & 31) == 0) red[t >> 5] = s;
    __syncthreads();
    if (t == 0) {
        float tot = 0.0f;
#pragma unroll
        for (int w = 0; w < SUM_THREADS / 32; w++) tot += red[w];
        g_part[blk] = tot;
        __threadfence();
        unsigned int v = atomicAdd(&g_sync, 1u);
        is_last = (v == (unsigned int)(SUM_BLOCKS - 1)) ? 1u : 0u;
    }
    __syncthreads();

    if (is_last) {
        __threadfence();
        float ps = (t < SUM_BLOCKS) ? __ldcg(&g_part[t]) : 0.0f;
#pragma unroll
        for (int o = 16; o > 0; o >>= 1)
            ps += __shfl_down_sync(0xffffffffu, ps, o);
        if ((t & 31) == 0) red[t >> 5] = ps;
        __syncthreads();
        if (t == 0) {
            float tot = 0.0f;
#pragma unroll
            for (int w = 0; w < SUM_THREADS / 32; w++) tot += red[w];
            out[0] = tot * (1.0f / 65536.0f);   // / (P * B)
            g_sync = 0u;
        }
    }
}

extern "C" void kernel_launch(void* const* d_in, const int* in_sizes, int n_in,
                              void* d_out, int out_size) {
    const float* gen   = (const float*)d_in[0];  // [B*P, 3]
    // d_in[1] = batch_gen (int32), unused: contiguous equal segments
    const float* label = (const float*)d_in[2];  // [B*Q, 5]
    float* out = (float*)d_out;

    sort_kernel<<<32, SORT_THREADS>>>(gen, label);
    nn_kernel<<<NQ_TOTAL / NN_THREADS, NN_THREADS>>>();
    sum_kernel<<<SUM_BLOCKS, SUM_THREADS>>>(out);
}

// round 12
// speedup vs baseline: 1.7670x; 1.7670x over previous
#include <cuda_runtime.h>
#include <math_constants.h>

// Chamfer distance, B=16 events, P=Q=4096, 3D.
// R12 = champion structure with RPT=4 x CSPLIT=2 (same 256 blocks x 8 warps
// as R6/R8, but each candidate LDS serves 4 rows instead of 2 -> L1 crossbar
// traffic halved) + __launch_bounds__(256,2) to unlock >40 registers.
// Per-row partial mins to scratch; deterministic combine kernel.

#define NB 16
#define NP 4096
#define THREADS 256
#define RPT 4
#define ROWS (THREADS * RPT)          // 1024 query rows per block
#define CHUNKS (NP / ROWS)            // 4
#define CSPLIT 2
#define TQ (NP / CSPLIT)              // 2048 candidates per block (32KB)
#define NROWS (2 * NB * NP)           // 131072 query rows (both dirs)

#define THREADS2 256
#define BLOCKS2 128
#define ROWS_PER_BLOCK2 (NROWS / BLOCKS2)              // 1024
#define ROWS_PER_THREAD2 (ROWS_PER_BLOCK2 / THREADS2)  // 4

__device__ float g_pmin[CSPLIT * NROWS];   // 1 MB scratch
__device__ float g_part2[BLOCKS2];
__device__ unsigned int g_sync2;           // zero-init; reset by last block

typedef unsigned long long u64;

__device__ __forceinline__ u64 pack2(float lo, float hi) {
    u64 r;
    asm("mov.b64 %0, {%1, %2};" : "=l"(r) : "f"(lo), "f"(hi));
    return r;
}
__device__ __forceinline__ u64 ffma2(u64 a, u64 b, u64 c) {
    u64 r;
    asm("fma.rn.f32x2 %0, %1, %2, %3;" : "=l"(r) : "l"(a), "l"(b), "l"(c));
    return r;
}
__device__ __forceinline__ void unpack2(u64 v, float& lo, float& hi) {
    asm("mov.b64 {%0, %1}, %2;" : "=f"(lo), "=f"(hi) : "l"(v));
}

__global__ __launch_bounds__(THREADS, 2)
void chamfer_kernel(const float* __restrict__ gen,
                    const float* __restrict__ label) {
    // Candidate quad per pair j: {(-2x0,-2x1),(-2y0,-2y1),(-2z0,-2z1),(n0,n1)}
    // +1 pad quad for the prefetch overread.
    __shared__ __align__(16) float tile[TQ / 2 + 1][8];   // 32KB + 32B

    const int zz    = blockIdx.z;          // 0..3 = dir*CSPLIT + split
    const int dir   = zz >> 1;             // 0: gen->gt, 1: gt->gen
    const int split = zz & 1;
    const int b     = blockIdx.y;
    const int chunk = blockIdx.x;
    const int t     = threadIdx.x;

    const float inv128 = 1.0f / 128.0f;

    // ---- query rows, register resident ----
    u64 xp0[RPT], xp1[RPT], xp2[RPT];
    float xn[RPT], mlo[RPT], mhi[RPT];
#pragma unroll
    for (int r = 0; r < RPT; r++) {
        int row = b * NP + chunk * ROWS + r * THREADS + t;
        float px, py, pz;
        if (dir == 0) {
            const float* s = gen + (size_t)row * 3;
            px = s[0]; py = s[1]; pz = s[2];
        } else {
            const float* s = label + (size_t)row * 5 + 1;
            px = (s[0] - 128.0f) * inv128;
            py = (s[1] - 128.0f) * inv128;
            pz = (s[2] - 128.0f) * inv128;
        }
        xn[r] = px * px + py * py + pz * pz;
        xp0[r] = pack2(px, px);
        xp1[r] = pack2(py, py);
        xp2[r] = pack2(pz, pz);
        mlo[r] = CUDART_INF_F;
        mhi[r] = CUDART_INF_F;
    }

    // ---- load this block's candidate half into smem ----
#pragma unroll
    for (int p = t; p < TQ; p += THREADS) {
        int idx = b * NP + split * TQ + p;
        float cx, cy, cz;
        if (dir == 0) {
            const float* s = label + (size_t)idx * 5 + 1;
            cx = (s[0] - 128.0f) * inv128;
            cy = (s[1] - 128.0f) * inv128;
            cz = (s[2] - 128.0f) * inv128;
        } else {
            const float* s = gen + (size_t)idx * 3;
            cx = s[0]; cy = s[1]; cz = s[2];
        }
        int j = p >> 1, h = p & 1;
        tile[j][0 + h] = -2.0f * cx;
        tile[j][2 + h] = -2.0f * cy;
        tile[j][4 + h] = -2.0f * cz;
        tile[j][6 + h] = cx * cx + cy * cy + cz * cz;
    }
    __syncthreads();

    const ulonglong2* tp = (const ulonglong2*)tile;

    // software pipeline: prefetch next iter's quad while computing current
    ulonglong2 c0 = tp[0];
    ulonglong2 c1 = tp[1];
#pragma unroll 8
    for (int j = 0; j < TQ / 2; j++) {
        ulonglong2 n0 = tp[j * 2 + 2];   // last iter reads the pad quad
        ulonglong2 n1 = tp[j * 2 + 3];
#pragma unroll
        for (int r = 0; r < RPT; r++) {
            u64 d = ffma2(xp2[r], c1.x,
                    ffma2(xp1[r], c0.y,
                    ffma2(xp0[r], c0.x, c1.y)));
            float lo, hi;
            unpack2(d, lo, hi);
            mlo[r] = fminf(mlo[r], lo);
            mhi[r] = fminf(mhi[r], hi);
        }
        c0 = n0;
        c1 = n1;
    }

    // ---- write partial per-row min (xn folded) ----
#pragma unroll
    for (int r = 0; r < RPT; r++) {
        int row_lin = (dir * NB + b) * NP + chunk * ROWS + r * THREADS + t;
        g_pmin[split * NROWS + row_lin] = xn[r] + fminf(mlo[r], mhi[r]);
    }
}

__global__ __launch_bounds__(THREADS2)
void combine_kernel(float* __restrict__ out) {
    __shared__ float red[THREADS2 / 32];
    __shared__ unsigned int is_last;
    const int t = threadIdx.x;
    const int blk = blockIdx.x;

    float s = 0.0f;
#pragma unroll
    for (int i = 0; i < ROWS_PER_THREAD2; i++) {
        int row = blk * ROWS_PER_BLOCK2 + i * THREADS2 + t;
        s += fminf(__ldcg(&g_pmin[row]), __ldcg(&g_pmin[NROWS + row]));
    }

#pragma unroll
    for (int o = 16; o > 0; o >>= 1)
        s += __shfl_down_sync(0xffffffffu, s, o);
    if ((t & 31) == 0) red[t >> 5] = s;
    __syncthreads();
    if (t == 0) {
        float tot = 0.0f;
#pragma unroll
        for (int w = 0; w < THREADS2 / 32; w++) tot += red[w];
        g_part2[blk] = tot;
        __threadfence();
        unsigned int v = atomicAdd(&g_sync2, 1u);
        is_last = (v == (unsigned int)(BLOCKS2 - 1)) ? 1u : 0u;
    }
    __syncthreads();

    if (is_last) {
        __threadfence();
        float ps = (t < BLOCKS2) ? __ldcg(&g_part2[t]) : 0.0f;
#pragma unroll
        for (int o = 16; o > 0; o >>= 1)
            ps += __shfl_down_sync(0xffffffffu, ps, o);
        if ((t & 31) == 0) red[t >> 5] = ps;
        __syncthreads();
        if (t == 0) {
            float tot = 0.0f;
#pragma unroll
            for (int w = 0; w < THREADS2 / 32; w++) tot += red[w];
            out[0] = tot * (1.0f / 65536.0f);   // / (P * B)
            g_sync2 = 0u;                       // reset for next call
        }
    }
}

extern "C" void kernel_launch(void* const* d_in, const int* in_sizes, int n_in,
                              void* d_out, int out_size) {
    const float* gen   = (const float*)d_in[0];  // [B*P, 3]
    // d_in[1] = batch_gen (int32), unused: contiguous equal segments
    const float* label = (const float*)d_in[2];  // [B*Q, 5]
    float* out = (float*)d_out;

    dim3 grid(CHUNKS, NB, 2 * CSPLIT);
    chamfer_kernel<<<grid, THREADS>>>(gen, label);
    combine_kernel<<<BLOCKS2, THREADS2>>>(out);
}

// round 13
// speedup vs baseline: 1.8464x; 1.0449x over previous
#include <cuda_runtime.h>
#include <math_constants.h>

// Chamfer distance, B=16 events, P=Q=4096, 3D.
// R13 = R12 per-warp structure (RPT=4, packed FFMA2 chain, prefetch) with
// fine-grained tiling: CSPLIT=16 -> 2048 uniform tiles of (1024 rows x 256
// cands). Kills the 256-block granularity tax (108 SMs ran 2 blocks, 40 ran
// 1 -> x1.156 critical path). Scratch g_pmin[row][16]; combine reads 64B/row.

#define NB 16
#define NP 4096
#define THREADS 256
#define RPT 4
#define ROWS (THREADS * RPT)          // 1024 query rows per tile
#define CHUNKS (NP / ROWS)            // 4
#define CSPLIT 16
#define TQ (NP / CSPLIT)              // 256 candidates per tile (4KB)
#define NROWS (2 * NB * NP)           // 131072 query rows (both dirs)

#define THREADS2 256
#define BLOCKS2 256
#define ROWS_PER_BLOCK2 (NROWS / BLOCKS2)              // 512
#define ROWS_PER_THREAD2 (ROWS_PER_BLOCK2 / THREADS2)  // 2

__device__ float g_pmin[NROWS][CSPLIT];    // 8 MB scratch, row-major
__device__ float g_part2[BLOCKS2];
__device__ unsigned int g_sync2;           // zero-init; reset by last block

typedef unsigned long long u64;

__device__ __forceinline__ u64 pack2(float lo, float hi) {
    u64 r;
    asm("mov.b64 %0, {%1, %2};" : "=l"(r) : "f"(lo), "f"(hi));
    return r;
}
__device__ __forceinline__ u64 ffma2(u64 a, u64 b, u64 c) {
    u64 r;
    asm("fma.rn.f32x2 %0, %1, %2, %3;" : "=l"(r) : "l"(a), "l"(b), "l"(c));
    return r;
}
__device__ __forceinline__ void unpack2(u64 v, float& lo, float& hi) {
    asm("mov.b64 {%0, %1}, %2;" : "=f"(lo), "=f"(hi) : "l"(v));
}

__global__ __launch_bounds__(THREADS, 4)
void chamfer_kernel(const float* __restrict__ gen,
                    const float* __restrict__ label) {
    // Candidate quad per pair j: {(-2x0,-2x1),(-2y0,-2y1),(-2z0,-2z1),(n0,n1)}
    // +1 pad quad for the prefetch overread.
    __shared__ __align__(16) float tile[TQ / 2 + 1][8];   // 4KB + 32B

    const int zz    = blockIdx.z;          // 0..31 = dir*CSPLIT + split
    const int dir   = zz >> 4;             // 0: gen->gt, 1: gt->gen
    const int split = zz & 15;
    const int b     = blockIdx.y;
    const int chunk = blockIdx.x;
    const int t     = threadIdx.x;

    const float inv128 = 1.0f / 128.0f;

    // ---- query rows, register resident ----
    u64 xp0[RPT], xp1[RPT], xp2[RPT];
    float xn[RPT], mlo[RPT], mhi[RPT];
#pragma unroll
    for (int r = 0; r < RPT; r++) {
        int row = b * NP + chunk * ROWS + r * THREADS + t;
        float px, py, pz;
        if (dir == 0) {
            const float* s = gen + (size_t)row * 3;
            px = s[0]; py = s[1]; pz = s[2];
        } else {
            const float* s = label + (size_t)row * 5 + 1;
            px = (s[0] - 128.0f) * inv128;
            py = (s[1] - 128.0f) * inv128;
            pz = (s[2] - 128.0f) * inv128;
        }
        xn[r] = px * px + py * py + pz * pz;
        xp0[r] = pack2(px, px);
        xp1[r] = pack2(py, py);
        xp2[r] = pack2(pz, pz);
        mlo[r] = CUDART_INF_F;
        mhi[r] = CUDART_INF_F;
    }

    // ---- load this tile's candidate slice into smem (1 elem/thread) ----
    {
        int p = t;                      // TQ == THREADS
        int idx = b * NP + split * TQ + p;
        float cx, cy, cz;
        if (dir == 0) {
            const float* s = label + (size_t)idx * 5 + 1;
            cx = (s[0] - 128.0f) * inv128;
            cy = (s[1] - 128.0f) * inv128;
            cz = (s[2] - 128.0f) * inv128;
        } else {
            const float* s = gen + (size_t)idx * 3;
            cx = s[0]; cy = s[1]; cz = s[2];
        }
        int j = p >> 1, h = p & 1;
        tile[j][0 + h] = -2.0f * cx;
        tile[j][2 + h] = -2.0f * cy;
        tile[j][4 + h] = -2.0f * cz;
        tile[j][6 + h] = cx * cx + cy * cy + cz * cz;
    }
    __syncthreads();

    const ulonglong2* tp = (const ulonglong2*)tile;

    // software pipeline: prefetch next iter's quad while computing current
    ulonglong2 c0 = tp[0];
    ulonglong2 c1 = tp[1];
#pragma unroll 8
    for (int j = 0; j < TQ / 2; j++) {
        ulonglong2 n0 = tp[j * 2 + 2];   // last iter reads the pad quad
        ulonglong2 n1 = tp[j * 2 + 3];
#pragma unroll
        for (int r = 0; r < RPT; r++) {
            u64 d = ffma2(xp2[r], c1.x,
                    ffma2(xp1[r], c0.y,
                    ffma2(xp0[r], c0.x, c1.y)));
            float lo, hi;
            unpack2(d, lo, hi);
            mlo[r] = fminf(mlo[r], lo);
            mhi[r] = fminf(mhi[r], hi);
        }
        c0 = n0;
        c1 = n1;
    }

    // ---- write partial per-row min (xn folded) ----
#pragma unroll
    for (int r = 0; r < RPT; r++) {
        int row_lin = (dir * NB + b) * NP + chunk * ROWS + r * THREADS + t;
        g_pmin[row_lin][split] = xn[r] + fminf(mlo[r], mhi[r]);
    }
}

__global__ __launch_bounds__(THREADS2)
void combine_kernel(float* __restrict__ out) {
    __shared__ float red[THREADS2 / 32];
    __shared__ unsigned int is_last;
    const int t = threadIdx.x;
    const int blk = blockIdx.x;

    float s = 0.0f;
#pragma unroll
    for (int i = 0; i < ROWS_PER_THREAD2; i++) {
        int row = blk * ROWS_PER_BLOCK2 + i * THREADS2 + t;
        const float4* p = (const float4*)&g_pmin[row][0];   // 64B contiguous
        float4 a = __ldcg(&p[0]);
        float4 bq = __ldcg(&p[1]);
        float4 c = __ldcg(&p[2]);
        float4 dq = __ldcg(&p[3]);
        float m = fminf(fminf(fminf(a.x, a.y), fminf(a.z, a.w)),
                        fminf(fminf(bq.x, bq.y), fminf(bq.z, bq.w)));
        m = fminf(m, fminf(fminf(fminf(c.x, c.y), fminf(c.z, c.w)),
                           fminf(fminf(dq.x, dq.y), fminf(dq.z, dq.w))));
        s += m;
    }

#pragma unroll
    for (int o = 16; o > 0; o >>= 1)
        s += __shfl_down_sync(0xffffffffu, s, o);
    if ((t & 31) == 0) red[t >> 5] = s;
    __syncthreads();
    if (t == 0) {
        float tot = 0.0f;
#pragma unroll
        for (int w = 0; w < THREADS2 / 32; w++) tot += red[w];
        g_part2[blk] = tot;
        __threadfence();
        unsigned int v = atomicAdd(&g_sync2, 1u);
        is_last = (v == (unsigned int)(BLOCKS2 - 1)) ? 1u : 0u;
    }
    __syncthreads();

    if (is_last) {
        __threadfence();
        float ps = __ldcg(&g_part2[t]);   // BLOCKS2 == THREADS2 == 256
#pragma unroll
        for (int o = 16; o > 0; o >>= 1)
            ps += __shfl_down_sync(0xffffffffu, ps, o);
        if ((t & 31) == 0) red[t >> 5] = ps;
        __syncthreads();
        if (t == 0) {
            float tot = 0.0f;
#pragma unroll
            for (int w = 0; w < THREADS2 / 32; w++) tot += red[w];
            out[0] = tot * (1.0f / 65536.0f);   // / (P * B)
            g_sync2 = 0u;                       // reset for next call
        }
    }
}

extern "C" void kernel_launch(void* const* d_in, const int* in_sizes, int n_in,
                              void* d_out, int out_size) {
    const float* gen   = (const float*)d_in[0];  // [B*P, 3]
    // d_in[1] = batch_gen (int32), unused: contiguous equal segments
    const float* label = (const float*)d_in[2];  // [B*Q, 5]
    float* out = (float*)d_out;

    dim3 grid(CHUNKS, NB, 2 * CSPLIT);
    chamfer_kernel<<<grid, THREADS>>>(gen, label);
    combine_kernel<<<BLOCKS2, THREADS2>>>(out);
}

// round 14
// speedup vs baseline: 1.9593x; 1.0612x over previous
#include <cuda_runtime.h>
#include <math_constants.h>

// Chamfer distance, B=16 events, P=Q=4096, 3D.
// R14 = R13 champion + (1) atomicMax(~float-bits) min-merge epilogue
// (0.5MB scratch, zero-init sentinel valid, combine resets after read) and
// (2) RPT=8 (each candidate LDS feeds 8 rows; 1024 uniform tiles).

#define NB 16
#define NP 4096
#define THREADS 256
#define RPT 8
#define ROWS (THREADS * RPT)          // 2048 query rows per tile
#define CHUNKS (NP / ROWS)            // 2
#define CSPLIT 16
#define TQ (NP / CSPLIT)              // 256 candidates per tile (4KB)
#define NROWS (2 * NB * NP)           // 131072 query rows (both dirs)

#define THREADS2 256
#define BLOCKS2 128
#define ROWS_PER_BLOCK2 (NROWS / BLOCKS2)              // 1024
#define ROWS_PER_THREAD2 (ROWS_PER_BLOCK2 / THREADS2)  // 4

// key = ~float_bits(min_d); max(key) == min(d) for finite d >= 0.
// zero-init is "empty" (every real key > 0); combine resets to 0 each call.
__device__ unsigned int g_key[NROWS];      // 0.5 MB
__device__ float g_part2[BLOCKS2];
__device__ unsigned int g_sync2;           // zero-init; reset by last block

typedef unsigned long long u64;

__device__ __forceinline__ u64 pack2(float lo, float hi) {
    u64 r;
    asm("mov.b64 %0, {%1, %2};" : "=l"(r) : "f"(lo), "f"(hi));
    return r;
}
__device__ __forceinline__ u64 ffma2(u64 a, u64 b, u64 c) {
    u64 r;
    asm("fma.rn.f32x2 %0, %1, %2, %3;" : "=l"(r) : "l"(a), "l"(b), "l"(c));
    return r;
}
__device__ __forceinline__ void unpack2(u64 v, float& lo, float& hi) {
    asm("mov.b64 {%0, %1}, %2;" : "=f"(lo), "=f"(hi) : "l"(v));
}

__global__ __launch_bounds__(THREADS, 2)
void chamfer_kernel(const float* __restrict__ gen,
                    const float* __restrict__ label) {
    // Candidate quad per pair j: {(-2x0,-2x1),(-2y0,-2y1),(-2z0,-2z1),(n0,n1)}
    // +1 pad quad for the prefetch overread.
    __shared__ __align__(16) float tile[TQ / 2 + 1][8];   // 4KB + 32B

    const int zz    = blockIdx.z;          // 0..31 = dir*CSPLIT + split
    const int dir   = zz >> 4;             // 0: gen->gt, 1: gt->gen
    const int split = zz & 15;
    const int b     = blockIdx.y;
    const int chunk = blockIdx.x;
    const int t     = threadIdx.x;

    const float inv128 = 1.0f / 128.0f;

    // ---- query rows, register resident ----
    u64 xp0[RPT], xp1[RPT], xp2[RPT];
    float xn[RPT], mlo[RPT], mhi[RPT];
#pragma unroll
    for (int r = 0; r < RPT; r++) {
        int row = b * NP + chunk * ROWS + r * THREADS + t;
        float px, py, pz;
        if (dir == 0) {
            const float* s = gen + (size_t)row * 3;
            px = s[0]; py = s[1]; pz = s[2];
        } else {
            const float* s = label + (size_t)row * 5 + 1;
            px = (s[0] - 128.0f) * inv128;
            py = (s[1] - 128.0f) * inv128;
            pz = (s[2] - 128.0f) * inv128;
        }
        xn[r] = px * px + py * py + pz * pz;
        xp0[r] = pack2(px, px);
        xp1[r] = pack2(py, py);
        xp2[r] = pack2(pz, pz);
        mlo[r] = CUDART_INF_F;
        mhi[r] = CUDART_INF_F;
    }

    // ---- load this tile's candidate slice into smem (1 elem/thread) ----
    {
        int p = t;                      // TQ == THREADS
        int idx = b * NP + split * TQ + p;
        float cx, cy, cz;
        if (dir == 0) {
            const float* s = label + (size_t)idx * 5 + 1;
            cx = (s[0] - 128.0f) * inv128;
            cy = (s[1] - 128.0f) * inv128;
            cz = (s[2] - 128.0f) * inv128;
        } else {
            const float* s = gen + (size_t)idx * 3;
            cx = s[0]; cy = s[1]; cz = s[2];
        }
        int j = p >> 1, h = p & 1;
        tile[j][0 + h] = -2.0f * cx;
        tile[j][2 + h] = -2.0f * cy;
        tile[j][4 + h] = -2.0f * cz;
        tile[j][6 + h] = cx * cx + cy * cy + cz * cz;
    }
    __syncthreads();

    const ulonglong2* tp = (const ulonglong2*)tile;

    // software pipeline: prefetch next iter's quad while computing current
    ulonglong2 c0 = tp[0];
    ulonglong2 c1 = tp[1];
#pragma unroll 4
    for (int j = 0; j < TQ / 2; j++) {
        ulonglong2 n0 = tp[j * 2 + 2];   // last iter reads the pad quad
        ulonglong2 n1 = tp[j * 2 + 3];
#pragma unroll
        for (int r = 0; r < RPT; r++) {
            u64 d = ffma2(xp2[r], c1.x,
                    ffma2(xp1[r], c0.y,
                    ffma2(xp0[r], c0.x, c1.y)));
            float lo, hi;
            unpack2(d, lo, hi);
            mlo[r] = fminf(mlo[r], lo);
            mhi[r] = fminf(mhi[r], hi);
        }
        c0 = n0;
        c1 = n1;
    }

    // ---- merge per-row min via atomicMax on complemented bits ----
#pragma unroll
    for (int r = 0; r < RPT; r++) {
        int row_lin = (dir * NB + b) * NP + chunk * ROWS + r * THREADS + t;
        float m = xn[r] + fminf(mlo[r], mhi[r]);
        atomicMax(&g_key[row_lin], ~__float_as_uint(m));
    }
}

__global__ __launch_bounds__(THREADS2)
void combine_kernel(float* __restrict__ out) {
    __shared__ float red[THREADS2 / 32];
    __shared__ unsigned int is_last;
    const int t = threadIdx.x;
    const int blk = blockIdx.x;

    float s = 0.0f;
#pragma unroll
    for (int i = 0; i < ROWS_PER_THREAD2; i++) {
        int row = blk * ROWS_PER_BLOCK2 + i * THREADS2 + t;
        unsigned int k = __ldcg(&g_key[row]);
        s += __uint_as_float(~k);
        g_key[row] = 0u;                 // reset sentinel for next graph replay
    }

#pragma unroll
    for (int o = 16; o > 0; o >>= 1)
        s += __shfl_down_sync(0xffffffffu, s, o);
    if ((t & 31) == 0) red[t >> 5] = s;
    __syncthreads();
    if (t == 0) {
        float tot = 0.0f;
#pragma unroll
        for (int w = 0; w < THREADS2 / 32; w++) tot += red[w];
        g_part2[blk] = tot;
        __threadfence();
        unsigned int v = atomicAdd(&g_sync2, 1u);
        is_last = (v == (unsigned int)(BLOCKS2 - 1)) ? 1u : 0u;
    }
    __syncthreads();

    if (is_last) {
        __threadfence();
        float ps = (t < BLOCKS2) ? __ldcg(&g_part2[t]) : 0.0f;
#pragma unroll
        for (int o = 16; o > 0; o >>= 1)
            ps += __shfl_down_sync(0xffffffffu, ps, o);
        if ((t & 31) == 0) red[t >> 5] = ps;
        __syncthreads();
        if (t == 0) {
            float tot = 0.0f;
#pragma unroll
            for (int w = 0; w < THREADS2 / 32; w++) tot += red[w];
            out[0] = tot * (1.0f / 65536.0f);   // / (P * B)
            g_sync2 = 0u;                       // reset for next call
        }
    }
}

extern "C" void kernel_launch(void* const* d_in, const int* in_sizes, int n_in,
                              void* d_out, int out_size) {
    const float* gen   = (const float*)d_in[0];  // [B*P, 3]
    // d_in[1] = batch_gen (int32), unused: contiguous equal segments
    const float* label = (const float*)d_in[2];  // [B*Q, 5]
    float* out = (float*)d_out;

    dim3 grid(CHUNKS, NB, 2 * CSPLIT);
    chamfer_kernel<<<grid, THREADS>>>(gen, label);
    combine_kernel<<<BLOCKS2, THREADS2>>>(out);
}

// round 15
// speedup vs baseline: 2.0122x; 1.0270x over previous
#include <cuda_runtime.h>
#include <math_constants.h>

// Chamfer distance, B=16 events, P=Q=4096, 3D.
// R15 = R14 champion main kernel (RPT=8, CSPLIT=16, packed FFMA2 chain,
// prefetch, atomicMax(~bits) min-merge) + wide flat combine kernel:
// 512 blocks x 256 thr, exactly ONE row per thread (latency, not serial).

#define NB 16
#define NP 4096
#define THREADS 256
#define RPT 8
#define ROWS (THREADS * RPT)          // 2048 query rows per tile
#define CHUNKS (NP / ROWS)            // 2
#define CSPLIT 16
#define TQ (NP / CSPLIT)              // 256 candidates per tile (4KB)
#define NROWS (2 * NB * NP)           // 131072 query rows (both dirs)

#define THREADS2 256
#define BLOCKS2 512                   // NROWS == BLOCKS2 * THREADS2

// key = ~float_bits(min_d); max(key) == min(d) for finite d >= 0.
// zero-init is "empty" (every real key > 0); combine resets to 0 each call.
__device__ unsigned int g_key[NROWS];      // 0.5 MB
__device__ float g_part2[BLOCKS2];
__device__ unsigned int g_sync2;           // zero-init; reset by last block

typedef unsigned long long u64;

__device__ __forceinline__ u64 pack2(float lo, float hi) {
    u64 r;
    asm("mov.b64 %0, {%1, %2};" : "=l"(r) : "f"(lo), "f"(hi));
    return r;
}
__device__ __forceinline__ u64 ffma2(u64 a, u64 b, u64 c) {
    u64 r;
    asm("fma.rn.f32x2 %0, %1, %2, %3;" : "=l"(r) : "l"(a), "l"(b), "l"(c));
    return r;
}
__device__ __forceinline__ void unpack2(u64 v, float& lo, float& hi) {
    asm("mov.b64 {%0, %1}, %2;" : "=f"(lo), "=f"(hi) : "l"(v));
}

__global__ __launch_bounds__(THREADS, 2)
void chamfer_kernel(const float* __restrict__ gen,
                    const float* __restrict__ label) {
    // Candidate quad per pair j: {(-2x0,-2x1),(-2y0,-2y1),(-2z0,-2z1),(n0,n1)}
    // +1 pad quad for the prefetch overread.
    __shared__ __align__(16) float tile[TQ / 2 + 1][8];   // 4KB + 32B

    const int zz    = blockIdx.z;          // 0..31 = dir*CSPLIT + split
    const int dir   = zz >> 4;             // 0: gen->gt, 1: gt->gen
    const int split = zz & 15;
    const int b     = blockIdx.y;
    const int chunk = blockIdx.x;
    const int t     = threadIdx.x;

    const float inv128 = 1.0f / 128.0f;

    // ---- query rows, register resident ----
    u64 xp0[RPT], xp1[RPT], xp2[RPT];
    float xn[RPT], mlo[RPT], mhi[RPT];
#pragma unroll
    for (int r = 0; r < RPT; r++) {
        int row = b * NP + chunk * ROWS + r * THREADS + t;
        float px, py, pz;
        if (dir == 0) {
            const float* s = gen + (size_t)row * 3;
            px = s[0]; py = s[1]; pz = s[2];
        } else {
            const float* s = label + (size_t)row * 5 + 1;
            px = (s[0] - 128.0f) * inv128;
            py = (s[1] - 128.0f) * inv128;
            pz = (s[2] - 128.0f) * inv128;
        }
        xn[r] = px * px + py * py + pz * pz;
        xp0[r] = pack2(px, px);
        xp1[r] = pack2(py, py);
        xp2[r] = pack2(pz, pz);
        mlo[r] = CUDART_INF_F;
        mhi[r] = CUDART_INF_F;
    }

    // ---- load this tile's candidate slice into smem (1 elem/thread) ----
    {
        int p = t;                      // TQ == THREADS
        int idx = b * NP + split * TQ + p;
        float cx, cy, cz;
        if (dir == 0) {
            const float* s = label + (size_t)idx * 5 + 1;
            cx = (s[0] - 128.0f) * inv128;
            cy = (s[1] - 128.0f) * inv128;
            cz = (s[2] - 128.0f) * inv128;
        } else {
            const float* s = gen + (size_t)idx * 3;
            cx = s[0]; cy = s[1]; cz = s[2];
        }
        int j = p >> 1, h = p & 1;
        tile[j][0 + h] = -2.0f * cx;
        tile[j][2 + h] = -2.0f * cy;
        tile[j][4 + h] = -2.0f * cz;
        tile[j][6 + h] = cx * cx + cy * cy + cz * cz;
    }
    __syncthreads();

    const ulonglong2* tp = (const ulonglong2*)tile;

    // software pipeline: prefetch next iter's quad while computing current
    ulonglong2 c0 = tp[0];
    ulonglong2 c1 = tp[1];
#pragma unroll 4
    for (int j = 0; j < TQ / 2; j++) {
        ulonglong2 n0 = tp[j * 2 + 2];   // last iter reads the pad quad
        ulonglong2 n1 = tp[j * 2 + 3];
#pragma unroll
        for (int r = 0; r < RPT; r++) {
            u64 d = ffma2(xp2[r], c1.x,
                    ffma2(xp1[r], c0.y,
                    ffma2(xp0[r], c0.x, c1.y)));
            float lo, hi;
            unpack2(d, lo, hi);
            mlo[r] = fminf(mlo[r], lo);
            mhi[r] = fminf(mhi[r], hi);
        }
        c0 = n0;
        c1 = n1;
    }

    // ---- merge per-row min via atomicMax on complemented bits ----
#pragma unroll
    for (int r = 0; r < RPT; r++) {
        int row_lin = (dir * NB + b) * NP + chunk * ROWS + r * THREADS + t;
        float m = xn[r] + fminf(mlo[r], mhi[r]);
        atomicMax(&g_key[row_lin], ~__float_as_uint(m));
    }
}

__global__ __launch_bounds__(THREADS2)
void combine_kernel(float* __restrict__ out) {
    __shared__ float red[THREADS2 / 32];
    __shared__ unsigned int is_last;
    const int t = threadIdx.x;
    const int row = blockIdx.x * THREADS2 + t;     // exactly one row/thread

    unsigned int k = __ldcg(&g_key[row]);
    g_key[row] = 0u;                  // reset sentinel for next graph replay
    float s = __uint_as_float(~k);

#pragma unroll
    for (int o = 16; o > 0; o >>= 1)
        s += __shfl_down_sync(0xffffffffu, s, o);
    if ((t & 31) == 0) red[t >> 5] = s;
    __syncthreads();
    if (t == 0) {
        float tot = 0.0f;
#pragma unroll
        for (int w = 0; w < THREADS2 / 32; w++) tot += red[w];
        g_part2[blockIdx.x] = tot;
        __threadfence();
        unsigned int v = atomicAdd(&g_sync2, 1u);
        is_last = (v == (unsigned int)(BLOCKS2 - 1)) ? 1u : 0u;
    }
    __syncthreads();

    if (is_last) {
        __threadfence();
        float ps = __ldcg(&g_part2[t]) + __ldcg(&g_part2[t + THREADS2]);
#pragma unroll
        for (int o = 16; o > 0; o >>= 1)
            ps += __shfl_down_sync(0xffffffffu, ps, o);
        if ((t & 31) == 0) red[t >> 5] = ps;
        __syncthreads();
        if (t == 0) {
            float tot = 0.0f;
#pragma unroll
            for (int w = 0; w < THREADS2 / 32; w++) tot += red[w];
            out[0] = tot * (1.0f / 65536.0f);   // / (P * B)
            g_sync2 = 0u;                       // reset for next call
        }
    }
}

extern "C" void kernel_launch(void* const* d_in, const int* in_sizes, int n_in,
                              void* d_out, int out_size) {
    const float* gen   = (const float*)d_in[0];  // [B*P, 3]
    // d_in[1] = batch_gen (int32), unused: contiguous equal segments
    const float* label = (const float*)d_in[2];  // [B*Q, 5]
    float* out = (float*)d_out;

    dim3 grid(CHUNKS, NB, 2 * CSPLIT);
    chamfer_kernel<<<grid, THREADS>>>(gen, label);
    combine_kernel<<<BLOCKS2, THREADS2>>>(out);
}

// round 16
// speedup vs baseline: 2.0618x; 1.0246x over previous
#include <cuda_runtime.h>
#include <math_constants.h>

// Chamfer distance, B=16 events, P=Q=4096, 3D.
// R16: SHARED distance matrix (one pass serves both directions).
// Lane owns 8 gt cands in registers (packed pairs); gen rows stream from
// smem as broadcast quads. Row-min: redux.sync.min.u32 per row (exact,
// deterministic), buffered per-lane, flushed 32-at-a-time via spread
// atomicMax(~bits). Col-min: per-lane register accumulators, flushed once.
// Epilogue: proven g_key + flat combine (R15).

#define NB 16
#define NP 4096
#define THREADS 256
#define ROWS_B 256
#define CHUNKS (NP / ROWS_B)     // 16
#define CSPLIT 2
#define SPLITW (NP / CSPLIT)     // 2048
#define NROWS (2 * NB * NP)      // 131072 (rows-dir then cols-dir)

#define THREADS2 256
#define BLOCKS2 512              // NROWS == BLOCKS2 * THREADS2

// key = ~float_bits(min_d); max(key) == min(d) for d >= 0.
// zero-init is "empty"; combine resets to 0 each call (graph-replay safe).
__device__ unsigned int g_key[NROWS];      // 0.5 MB
__device__ float g_part2[BLOCKS2];
__device__ unsigned int g_sync2;           // zero-init; reset by combine

typedef unsigned long long u64;

__device__ __forceinline__ u64 pack2(float lo, float hi) {
    u64 r;
    asm("mov.b64 %0, {%1, %2};" : "=l"(r) : "f"(lo), "f"(hi));
    return r;
}
__device__ __forceinline__ u64 ffma2(u64 a, u64 b, u64 c) {
    u64 r;
    asm("fma.rn.f32x2 %0, %1, %2, %3;" : "=l"(r) : "l"(a), "l"(b), "l"(c));
    return r;
}
__device__ __forceinline__ u64 add2(u64 a, u64 b) {
    u64 r;
    asm("add.rn.f32x2 %0, %1, %2;" : "=l"(r) : "l"(a), "l"(b));
    return r;
}
__device__ __forceinline__ void unpack2(u64 v, float& lo, float& hi) {
    asm("mov.b64 {%0, %1}, %2;" : "=f"(lo), "=f"(hi) : "l"(v));
}
__device__ __forceinline__ unsigned int redux_min(unsigned int v) {
    unsigned int r;
    asm("redux.sync.min.u32 %0, %1, 0xffffffff;" : "=r"(r) : "r"(v));
    return r;
}

__global__ __launch_bounds__(THREADS, 2)
void chamfer_kernel(const float* __restrict__ gen,
                    const float* __restrict__ label) {
    // Row quad: {(-2gx,-2gx),(-2gy,-2gy),(-2gz,-2gz),(gn,gn)} = 4 u64.
    __shared__ __align__(16) u64 rowq[ROWS_B + 1][4];   // 8KB + pad row

    const int split = blockIdx.z;          // gt-cand half
    const int b     = blockIdx.y;          // event
    const int chunk = blockIdx.x;          // gen-row chunk
    const int t     = threadIdx.x;
    const int w     = t >> 5, lane = t & 31;

    const float inv128 = 1.0f / 128.0f;

    // ---- gen rows -> smem quads (1 row/thread) ----
    {
        int row = b * NP + chunk * ROWS_B + t;
        const float* s = gen + (size_t)row * 3;
        float gx = s[0], gy = s[1], gz = s[2];
        float gn = gx * gx + gy * gy + gz * gz;
        rowq[t][0] = pack2(-2.0f * gx, -2.0f * gx);
        rowq[t][1] = pack2(-2.0f * gy, -2.0f * gy);
        rowq[t][2] = pack2(-2.0f * gz, -2.0f * gz);
        rowq[t][3] = pack2(gn, gn);
    }
    if (t < 4) rowq[ROWS_B][t] = 0;        // pad for prefetch overread

    // ---- gt cands: 8 per lane (4 packed pairs), register resident ----
    u64 cx2[4], cy2[4], cz2[4], cn2[4];
    float mcol[8];
#pragma unroll
    for (int k = 0; k < 4; k++) {
        int c0 = b * NP + split * SPLITW + w * 256 + (k * 32 + lane) * 2;
        const float* sa = label + (size_t)c0 * 5 + 1;
        const float* sb = label + (size_t)(c0 + 1) * 5 + 1;
        float ax = (sa[0] - 128.0f) * inv128;
        float ay = (sa[1] - 128.0f) * inv128;
        float az = (sa[2] - 128.0f) * inv128;
        float bx = (sb[0] - 128.0f) * inv128;
        float by = (sb[1] - 128.0f) * inv128;
        float bz = (sb[2] - 128.0f) * inv128;
        cx2[k] = pack2(ax, bx);
        cy2[k] = pack2(ay, by);
        cz2[k] = pack2(az, bz);
        cn2[k] = pack2(ax * ax + ay * ay + az * az,
                       bx * bx + by * by + bz * bz);
        mcol[2 * k]     = CUDART_INF_F;
        mcol[2 * k + 1] = CUDART_INF_F;
    }
    __syncthreads();

    const ulonglong2* rp = (const ulonglong2*)rowq;
    const int rowbase = b * NP + chunk * ROWS_B;

    ulonglong2 ra = rp[0];                  // {r0=-2gx pair, r1=-2gy pair}
    ulonglong2 rb = rp[1];                  // {r2=-2gz pair, r3=gn pair}
    float rbuf = 0.0f;

    for (int g = 0; g < ROWS_B / 32; g++) {
#pragma unroll 4
        for (int ii = 0; ii < 32; ii++) {
            int i = g * 32 + ii;
            ulonglong2 na = rp[2 * i + 2];  // prefetch next row (pad at end)
            ulonglong2 nb = rp[2 * i + 3];
            float rm = CUDART_INF_F;
#pragma unroll
            for (int k = 0; k < 4; k++) {
                // d = (cn + gn) - 2 c.g   (full distance, serves both dirs)
                u64 d = ffma2(cz2[k], rb.x,
                        ffma2(cy2[k], ra.y,
                        ffma2(cx2[k], ra.x, add2(cn2[k], rb.y))));
                float a, bq;
                unpack2(d, a, bq);
                mcol[2 * k]     = fminf(mcol[2 * k], a);
                mcol[2 * k + 1] = fminf(mcol[2 * k + 1], bq);
                rm = fminf(rm, fminf(a, bq));
            }
            // warp row-min over this warp's 256 cands (exact, deterministic)
            unsigned int r = redux_min(__float_as_uint(rm));
            if (lane == ii) rbuf = __uint_as_float(r);
            ra = na;
            rb = nb;
        }
        // flush 32 row-mins, one per lane, spread addresses
        atomicMax(&g_key[rowbase + g * 32 + lane], ~__float_as_uint(rbuf));
    }

    // ---- flush col-mins (gt -> gen direction) ----
#pragma unroll
    for (int k = 0; k < 4; k++) {
        int c = NB * NP + b * NP + split * SPLITW + w * 256 + (k * 32 + lane) * 2;
        atomicMax(&g_key[c],     ~__float_as_uint(mcol[2 * k]));
        atomicMax(&g_key[c + 1], ~__float_as_uint(mcol[2 * k + 1]));
    }
}

__global__ __launch_bounds__(THREADS2)
void combine_kernel(float* __restrict__ out) {
    __shared__ float red[THREADS2 / 32];
    __shared__ unsigned int is_last;
    const int t = threadIdx.x;
    const int row = blockIdx.x * THREADS2 + t;     // exactly one entry/thread

    unsigned int k = __ldcg(&g_key[row]);
    g_key[row] = 0u;                  // reset sentinel for next graph replay
    float s = __uint_as_float(~k);

#pragma unroll
    for (int o = 16; o > 0; o >>= 1)
        s += __shfl_down_sync(0xffffffffu, s, o);
    if ((t & 31) == 0) red[t >> 5] = s;
    __syncthreads();
    if (t == 0) {
        float tot = 0.0f;
#pragma unroll
        for (int w = 0; w < THREADS2 / 32; w++) tot += red[w];
        g_part2[blockIdx.x] = tot;
        __threadfence();
        unsigned int v = atomicAdd(&g_sync2, 1u);
        is_last = (v == (unsigned int)(BLOCKS2 - 1)) ? 1u : 0u;
    }
    __syncthreads();

    if (is_last) {
        __threadfence();
        float ps = __ldcg(&g_part2[t]) + __ldcg(&g_part2[t + THREADS2]);
#pragma unroll
        for (int o = 16; o > 0; o >>= 1)
            ps += __shfl_down_sync(0xffffffffu, ps, o);
        if ((t & 31) == 0) red[t >> 5] = ps;
        __syncthreads();
        if (t == 0) {
            float tot = 0.0f;
#pragma unroll
            for (int w = 0; w < THREADS2 / 32; w++) tot += red[w];
            out[0] = tot * (1.0f / 65536.0f);   // / (P * B)
            g_sync2 = 0u;                       // reset for next call
        }
    }
}

extern "C" void kernel_launch(void* const* d_in, const int* in_sizes, int n_in,
                              void* d_out, int out_size) {
    const float* gen   = (const float*)d_in[0];  // [B*P, 3]
    // d_in[1] = batch_gen (int32), unused: contiguous equal segments
    const float* label = (const float*)d_in[2];  // [B*Q, 5]
    float* out = (float*)d_out;

    dim3 grid(CHUNKS, NB, CSPLIT);               // 16 x 16 x 2 = 512 blocks
    chamfer_kernel<<<grid, THREADS>>>(gen, label);
    combine_kernel<<<BLOCKS2, THREADS2>>>(out);
}

// round 17
// speedup vs baseline: 2.3115x; 1.1211x over previous
#include <cuda_runtime.h>
#include <math_constants.h>

// Chamfer distance, B=16 events, P=Q=4096, 3D.
// R17 = R16 shared-distance-matrix kernel with:
//   (1) ROWS_B=128 -> 1024 uniform blocks (kills the 3.46-blocks/SM tax)
//   (2) tree row-min (shorter dep chain into redux)
//   (3) unroll 8 row loop.
// Lane owns 8 gt cands (packed pairs); rows broadcast from smem; row-min via
// redux.sync.min.u32 (exact, deterministic); col-min in registers.
// Epilogue: g_key atomicMax(~bits) + flat combine.

#define NB 16
#define NP 4096
#define THREADS 256
#define ROWS_B 128
#define CHUNKS (NP / ROWS_B)     // 32
#define CSPLIT 2
#define SPLITW (NP / CSPLIT)     // 2048
#define NROWS (2 * NB * NP)      // 131072 (rows-dir then cols-dir)

#define THREADS2 256
#define BLOCKS2 512              // NROWS == BLOCKS2 * THREADS2

// key = ~float_bits(min_d); max(key) == min(d) for d >= 0.
// zero-init is "empty"; combine resets to 0 each call (graph-replay safe).
__device__ unsigned int g_key[NROWS];      // 0.5 MB
__device__ float g_part2[BLOCKS2];
__device__ unsigned int g_sync2;           // zero-init; reset by combine

typedef unsigned long long u64;

__device__ __forceinline__ u64 pack2(float lo, float hi) {
    u64 r;
    asm("mov.b64 %0, {%1, %2};" : "=l"(r) : "f"(lo), "f"(hi));
    return r;
}
__device__ __forceinline__ u64 ffma2(u64 a, u64 b, u64 c) {
    u64 r;
    asm("fma.rn.f32x2 %0, %1, %2, %3;" : "=l"(r) : "l"(a), "l"(b), "l"(c));
    return r;
}
__device__ __forceinline__ u64 add2(u64 a, u64 b) {
    u64 r;
    asm("add.rn.f32x2 %0, %1, %2;" : "=l"(r) : "l"(a), "l"(b));
    return r;
}
__device__ __forceinline__ void unpack2(u64 v, float& lo, float& hi) {
    asm("mov.b64 {%0, %1}, %2;" : "=f"(lo), "=f"(hi) : "l"(v));
}
__device__ __forceinline__ unsigned int redux_min(unsigned int v) {
    unsigned int r;
    asm("redux.sync.min.u32 %0, %1, 0xffffffff;" : "=r"(r) : "r"(v));
    return r;
}

__global__ __launch_bounds__(THREADS, 2)
void chamfer_kernel(const float* __restrict__ gen,
                    const float* __restrict__ label) {
    // Row quad: {(-2gx,-2gx),(-2gy,-2gy),(-2gz,-2gz),(gn,gn)} = 4 u64.
    __shared__ __align__(16) u64 rowq[ROWS_B + 1][4];   // 4KB + pad row

    const int split = blockIdx.z;          // gt-cand half
    const int b     = blockIdx.y;          // event
    const int chunk = blockIdx.x;          // gen-row chunk
    const int t     = threadIdx.x;
    const int w     = t >> 5, lane = t & 31;

    const float inv128 = 1.0f / 128.0f;

    // ---- gen rows -> smem quads (1 row/thread, first ROWS_B threads) ----
    if (t < ROWS_B) {
        int row = b * NP + chunk * ROWS_B + t;
        const float* s = gen + (size_t)row * 3;
        float gx = s[0], gy = s[1], gz = s[2];
        float gn = gx * gx + gy * gy + gz * gz;
        rowq[t][0] = pack2(-2.0f * gx, -2.0f * gx);
        rowq[t][1] = pack2(-2.0f * gy, -2.0f * gy);
        rowq[t][2] = pack2(-2.0f * gz, -2.0f * gz);
        rowq[t][3] = pack2(gn, gn);
    }
    if (t >= ROWS_B && t < ROWS_B + 4) rowq[ROWS_B][t - ROWS_B] = 0;  // pad

    // ---- gt cands: 8 per lane (4 packed pairs), register resident ----
    u64 cx2[4], cy2[4], cz2[4], cn2[4];
    float mcol[8];
#pragma unroll
    for (int k = 0; k < 4; k++) {
        int c0 = b * NP + split * SPLITW + w * 256 + (k * 32 + lane) * 2;
        const float* sa = label + (size_t)c0 * 5 + 1;
        const float* sb = label + (size_t)(c0 + 1) * 5 + 1;
        float ax = (sa[0] - 128.0f) * inv128;
        float ay = (sa[1] - 128.0f) * inv128;
        float az = (sa[2] - 128.0f) * inv128;
        float bx = (sb[0] - 128.0f) * inv128;
        float by = (sb[1] - 128.0f) * inv128;
        float bz = (sb[2] - 128.0f) * inv128;
        cx2[k] = pack2(ax, bx);
        cy2[k] = pack2(ay, by);
        cz2[k] = pack2(az, bz);
        cn2[k] = pack2(ax * ax + ay * ay + az * az,
                       bx * bx + by * by + bz * bz);
        mcol[2 * k]     = CUDART_INF_F;
        mcol[2 * k + 1] = CUDART_INF_F;
    }
    __syncthreads();

    const ulonglong2* rp = (const ulonglong2*)rowq;
    const int rowbase = b * NP + chunk * ROWS_B;

    ulonglong2 ra = rp[0];                  // {-2gx pair, -2gy pair}
    ulonglong2 rb = rp[1];                  // {-2gz pair, gn pair}
    float rbuf = 0.0f;

    for (int g = 0; g < ROWS_B / 32; g++) {
#pragma unroll 8
        for (int ii = 0; ii < 32; ii++) {
            int i = g * 32 + ii;
            ulonglong2 na = rp[2 * i + 2];  // prefetch next row (pad at end)
            ulonglong2 nb = rp[2 * i + 3];
            float tk[4];
#pragma unroll
            for (int k = 0; k < 4; k++) {
                // d = (cn + gn) - 2 c.g   (full distance, serves both dirs)
                u64 d = ffma2(cz2[k], rb.x,
                        ffma2(cy2[k], ra.y,
                        ffma2(cx2[k], ra.x, add2(cn2[k], rb.y))));
                float a, bq;
                unpack2(d, a, bq);
                mcol[2 * k]     = fminf(mcol[2 * k], a);
                mcol[2 * k + 1] = fminf(mcol[2 * k + 1], bq);
                tk[k] = fminf(a, bq);
            }
            float rm = fminf(fminf(tk[0], tk[1]), fminf(tk[2], tk[3]));
            // warp row-min over this warp's 256 cands (exact, deterministic)
            unsigned int r = redux_min(__float_as_uint(rm));
            if (lane == ii) rbuf = __uint_as_float(r);
            ra = na;
            rb = nb;
        }
        // flush 32 row-mins, one per lane, spread addresses
        atomicMax(&g_key[rowbase + g * 32 + lane], ~__float_as_uint(rbuf));
    }

    // ---- flush col-mins (gt -> gen direction) ----
#pragma unroll
    for (int k = 0; k < 4; k++) {
        int c = NB * NP + b * NP + split * SPLITW + w * 256 + (k * 32 + lane) * 2;
        atomicMax(&g_key[c],     ~__float_as_uint(mcol[2 * k]));
        atomicMax(&g_key[c + 1], ~__float_as_uint(mcol[2 * k + 1]));
    }
}

__global__ __launch_bounds__(THREADS2)
void combine_kernel(float* __restrict__ out) {
    __shared__ float red[THREADS2 / 32];
    __shared__ unsigned int is_last;
    const int t = threadIdx.x;
    const int row = blockIdx.x * THREADS2 + t;     // exactly one entry/thread

    unsigned int k = __ldcg(&g_key[row]);
    g_key[row] = 0u;                  // reset sentinel for next graph replay
    float s = __uint_as_float(~k);

#pragma unroll
    for (int o = 16; o > 0; o >>= 1)
        s += __shfl_down_sync(0xffffffffu, s, o);
    if ((t & 31) == 0) red[t >> 5] = s;
    __syncthreads();
    if (t == 0) {
        float tot = 0.0f;
#pragma unroll
        for (int w = 0; w < THREADS2 / 32; w++) tot += red[w];
        g_part2[blockIdx.x] = tot;
        __threadfence();
        unsigned int v = atomicAdd(&g_sync2, 1u);
        is_last = (v == (unsigned int)(BLOCKS2 - 1)) ? 1u : 0u;
    }
    __syncthreads();

    if (is_last) {
        __threadfence();
        float ps = __ldcg(&g_part2[t]) + __ldcg(&g_part2[t + THREADS2]);
#pragma unroll
        for (int o = 16; o > 0; o >>= 1)
            ps += __shfl_down_sync(0xffffffffu, ps, o);
        if ((t & 31) == 0) red[t >> 5] = ps;
        __syncthreads();
        if (t == 0) {
            float tot = 0.0f;
#pragma unroll
            for (int w = 0; w < THREADS2 / 32; w++) tot += red[w];
            out[0] = tot * (1.0f / 65536.0f);   // / (P * B)
            g_sync2 = 0u;                       // reset for next call
        }
    }
}

extern "C" void kernel_launch(void* const* d_in, const int* in_sizes, int n_in,
                              void* d_out, int out_size) {
    const float* gen   = (const float*)d_in[0];  // [B*P, 3]
    // d_in[1] = batch_gen (int32), unused: contiguous equal segments
    const float* label = (const float*)d_in[2];  // [B*Q, 5]
    float* out = (float*)d_out;

    dim3 grid(CHUNKS, NB, CSPLIT);               // 32 x 16 x 2 = 1024 blocks
    chamfer_kernel<<<grid, THREADS>>>(gen, label);
    combine_kernel<<<BLOCKS2, THREADS2>>>(out);
}